// round 10
// baseline (speedup 1.0000x reference)
#include <cuda_runtime.h>
#include <cuda_bf16.h>
#include <cuda_fp16.h>
#include <cstdint>

#define NN 100000
#define EMAXC 1700000

// ---------------- scratch (static device globals; no allocs) ----------------
__device__ uint32_t g_h1h[NN * 32];  // layer1 features, fp16x2-packed (64 cols)
__device__ float    g_x1[NN * 64];   // layer1 output (f32, gemm2 input)
__device__ uint32_t g_h2h[NN * 16];  // layer2 features, fp16x2-packed (32 cols)
__device__ float    g_x2[NN * 32];   // layer2 output (f32)
__device__ float    g_as[NN];
__device__ float    g_ad[NN];
__device__ int      g_deg[NN];
__device__ int      g_rowptr[NN + 1];
__device__ int      g_cur[NN];
__device__ int      g_blk[128];
__device__ int      g_esrc[EMAXC];
__device__ uint4    g_bf[4096];      // preconverted W1 fragments

typedef unsigned long long u64;

__device__ __forceinline__ u64 ffma2(u64 a, u64 b, u64 c) {
    u64 d;
    asm("fma.rn.f32x2 %0, %1, %2, %3;" : "=l"(d) : "l"(a), "l"(b), "l"(c));
    return d;
}
__device__ __forceinline__ u64 pack2(float x, float y) {
    u64 r;
    asm("mov.b64 %0, {%1,%2};" : "=l"(r) : "f"(x), "f"(y));
    return r;
}
__device__ __forceinline__ void unpack2(u64 v, float& x, float& y) {
    asm("mov.b64 {%0,%1}, %2;" : "=f"(x), "=f"(y) : "l"(v));
}

__device__ __forceinline__ void mma16816(float* c, uint32_t a0, uint32_t a1,
                                         uint32_t a2, uint32_t a3,
                                         uint32_t b0, uint32_t b1) {
    asm volatile(
        "mma.sync.aligned.m16n8k16.row.col.f32.bf16.bf16.f32 "
        "{%0,%1,%2,%3}, {%4,%5,%6,%7}, {%8,%9}, {%0,%1,%2,%3};"
        : "+f"(c[0]), "+f"(c[1]), "+f"(c[2]), "+f"(c[3])
        : "r"(a0), "r"(a1), "r"(a2), "r"(a3), "r"(b0), "r"(b1));
}

__device__ __forceinline__ uint32_t bfhi2(float x, float y) {
    __nv_bfloat162 h = __floats2bfloat162_rn(x, y);
    return *(uint32_t*)&h;
}
__device__ __forceinline__ uint32_t bflo2(float x, float y, uint32_t hi) {
    __nv_bfloat162 h = *(__nv_bfloat162*)&hi;
    float2 f = __bfloat1622float2(h);
    __nv_bfloat162 l = __floats2bfloat162_rn(x - f.x, y - f.y);
    return *(uint32_t*)&l;
}
__device__ __forceinline__ uint32_t fp16x2(float x, float y) {
    __half2 h = __floats2half2_rn(x, y);
    return *(uint32_t*)&h;
}
__device__ __forceinline__ float2 h2f(uint32_t u) {
    return __half22float2(*(__half2*)&u);
}

// precompute W1 fragments: idx = kk*256 + n*4 + tig
__global__ void preconv_b_kernel(const float* __restrict__ W,
                                 uint4* __restrict__ Bf) {
    int idx = blockIdx.x * 256 + threadIdx.x;
    if (idx >= 4096) return;
    int tig = idx & 3, n = (idx >> 2) & 63, kk = idx >> 8;
    int k = kk * 16 + 2 * tig;
    float w00 = __ldg(&W[(size_t)k * 64 + n]);
    float w01 = __ldg(&W[(size_t)(k + 1) * 64 + n]);
    float w10 = __ldg(&W[(size_t)(k + 8) * 64 + n]);
    float w11 = __ldg(&W[(size_t)(k + 9) * 64 + n]);
    uint4 o;
    o.x = bfhi2(w00, w01);
    o.y = bfhi2(w10, w11);
    o.z = bflo2(w00, w01, o.x);
    o.w = bflo2(w10, w11, o.y);
    Bf[idx] = o;
}

// ======= gemm1: h1h[M,64] = fp16(x @ W1); alpha epilogue; 32 rows/warp =====
__global__ void __launch_bounds__(256)
gemm1_mma_kernel(const float* __restrict__ A,   // [M,256]
                 const uint4* __restrict__ Bf,
                 uint32_t* __restrict__ Ch,     // [M,32] fp16x2
                 int M,
                 const float* __restrict__ av, const float* __restrict__ bv,
                 float* __restrict__ as_out, float* __restrict__ ad_out) {
    const int tid = threadIdx.x;
    const int wid = tid >> 5, lane = tid & 31;
    const int gid = lane >> 2, tig = lane & 3;
    const int r0 = blockIdx.x * 256 + wid * 32 + gid;  // rows r0,+8,+16,+24

    const float* ap[4];
#pragma unroll
    for (int g = 0; g < 4; g++)
        ap[g] = A + (size_t)min(r0 + 8 * g, M - 1) * 256 + 2 * tig;

    float acc[2][8][4];
#pragma unroll
    for (int g2 = 0; g2 < 2; g2++)
#pragma unroll
        for (int t = 0; t < 8; t++)
#pragma unroll
            for (int j = 0; j < 4; j++) acc[g2][t][j] = 0.f;

#pragma unroll 2
    for (int kk = 0; kk < 16; kk++) {
        uint32_t ah[4], ah8[4], al[4], al8[4];
#pragma unroll
        for (int g = 0; g < 4; g++) {
            float2 v0 = __ldg((const float2*)(ap[g] + kk * 16));
            float2 v1 = __ldg((const float2*)(ap[g] + kk * 16 + 8));
            ah[g]  = bfhi2(v0.x, v0.y);
            ah8[g] = bfhi2(v1.x, v1.y);
            al[g]  = bflo2(v0.x, v0.y, ah[g]);
            al8[g] = bflo2(v1.x, v1.y, ah8[g]);
        }
        const uint4* bp = Bf + kk * 256 + gid * 4 + tig;
#pragma unroll
        for (int nt = 0; nt < 8; nt++) {
            uint4 b = __ldg(bp + nt * 32);
            mma16816(acc[0][nt], ah[0], ah[1], ah8[0], ah8[1], b.x, b.y);
            mma16816(acc[0][nt], ah[0], ah[1], ah8[0], ah8[1], b.z, b.w);
            mma16816(acc[0][nt], al[0], al[1], al8[0], al8[1], b.x, b.y);
            mma16816(acc[1][nt], ah[2], ah[3], ah8[2], ah8[3], b.x, b.y);
            mma16816(acc[1][nt], ah[2], ah[3], ah8[2], ah8[3], b.z, b.w);
            mma16816(acc[1][nt], al[2], al[3], al8[2], al8[3], b.x, b.y);
        }
    }

    // ---- epilogue: fp16 store + alpha dots ----
#pragma unroll
    for (int g2 = 0; g2 < 2; g2++) {
        int grA = r0 + 16 * g2;
        int grB = grA + 8;
        float sA = 0.f, dA = 0.f, sB = 0.f, dB = 0.f;
#pragma unroll
        for (int nt = 0; nt < 8; nt++) {
            int col = nt * 8 + 2 * tig;
            float a0 = __ldg(&av[col]), a1 = __ldg(&av[col + 1]);
            float b0 = __ldg(&bv[col]), b1 = __ldg(&bv[col + 1]);
            float* c = acc[g2][nt];
            if (grA < M)
                Ch[(size_t)grA * 32 + nt * 4 + tig] = fp16x2(c[0], c[1]);
            if (grB < M)
                Ch[(size_t)grB * 32 + nt * 4 + tig] = fp16x2(c[2], c[3]);
            sA += c[0] * a0 + c[1] * a1;
            dA += c[0] * b0 + c[1] * b1;
            sB += c[2] * a0 + c[3] * a1;
            dB += c[2] * b0 + c[3] * b1;
        }
#pragma unroll
        for (int off = 1; off < 4; off <<= 1) {
            sA += __shfl_xor_sync(0xffffffffu, sA, off);
            dA += __shfl_xor_sync(0xffffffffu, dA, off);
            sB += __shfl_xor_sync(0xffffffffu, sB, off);
            dB += __shfl_xor_sync(0xffffffffu, dB, off);
        }
        if (tig == 0) {
            if (grA < M) { as_out[grA] = sA; ad_out[grA] = dA; }
            if (grB < M) { as_out[grB] = sB; ad_out[grB] = dB; }
        }
    }
}

// ======================= CSR build =======================
__global__ void hist_kernel(const int* __restrict__ ei, int E, int nE,
                            int* __restrict__ deg) {
    int e = blockIdx.x * blockDim.x + threadIdx.x;
    if (e >= nE) return;
    int d = (e < E) ? __ldg(&ei[E + e]) : e - E;
    atomicAdd(&deg[d], 1);
}

__global__ void scan_block_kernel(const int* __restrict__ deg,
                                  int* __restrict__ rowptr,
                                  int* __restrict__ blk, int n) {
    __shared__ int sh[1024];
    int i = blockIdx.x * 1024 + threadIdx.x;
    int v = (i < n) ? deg[i] : 0;
    sh[threadIdx.x] = v;
    __syncthreads();
#pragma unroll
    for (int off = 1; off < 1024; off <<= 1) {
        int t = (threadIdx.x >= off) ? sh[threadIdx.x - off] : 0;
        __syncthreads();
        sh[threadIdx.x] += t;
        __syncthreads();
    }
    if (i < n) rowptr[i + 1] = sh[threadIdx.x];
    if (threadIdx.x == 1023) blk[blockIdx.x] = sh[1023];
}

__global__ void scan_tops_kernel(int* __restrict__ blk, int nb) {
    __shared__ int sh[128];
    int v = (threadIdx.x < nb) ? blk[threadIdx.x] : 0;
    sh[threadIdx.x] = v;
    __syncthreads();
#pragma unroll
    for (int off = 1; off < 128; off <<= 1) {
        int t = (threadIdx.x >= off) ? sh[threadIdx.x - off] : 0;
        __syncthreads();
        sh[threadIdx.x] += t;
        __syncthreads();
    }
    if (threadIdx.x < nb)
        blk[threadIdx.x] = (threadIdx.x == 0) ? 0 : sh[threadIdx.x - 1];
}

__global__ void scan_add_kernel(int* __restrict__ rowptr,
                                const int* __restrict__ blk,
                                const int* __restrict__ deg,
                                int* __restrict__ cur, int n) {
    int i = blockIdx.x * 1024 + threadIdx.x;
    if (i >= n) return;
    int v = rowptr[i + 1] + blk[i / 1024];
    rowptr[i + 1] = v;
    cur[i] = v - deg[i];
    if (i == 0) rowptr[0] = 0;
}

__global__ void scatter_kernel(const int* __restrict__ ei, int E, int nE,
                               int* __restrict__ cur, int* __restrict__ esrc) {
    int e = blockIdx.x * blockDim.x + threadIdx.x;
    if (e >= nE) return;
    int s, d;
    if (e < E) { s = __ldg(&ei[e]); d = __ldg(&ei[E + e]); } else { s = d = e - E; }
    int p = atomicAdd(&cur[d], 1);
    esrc[p] = s;
}

// ---------------- FFMA2 GEMM (layer 2), fp16 output + alpha epilogue -------
template <int BM, int BN, int BK, int TM, int TN>
__global__ void gemm_fused_kernel(const float* __restrict__ A,
                                  const float* __restrict__ B,
                                  uint32_t* __restrict__ Ch, int M, int K,
                                  const float* __restrict__ av,
                                  const float* __restrict__ bv,
                                  float* __restrict__ as_out,
                                  float* __restrict__ ad_out) {
    __shared__ u64  As[BK][BM + 1];
    __shared__ float Bs[BK][BN];
    const int tx = threadIdx.x, ty = threadIdx.y;
    constexpr int TG = BN / TN;
    const int tid = ty * TG + tx;
    constexpr int NT = TG * (BM / TM);
    const int rowBase = blockIdx.x * BM;

    u64 acc[TM][TN / 2];
#pragma unroll
    for (int i = 0; i < TM; i++)
#pragma unroll
        for (int j = 0; j < TN / 2; j++) acc[i][j] = 0ull;

    for (int k0 = 0; k0 < K; k0 += BK) {
#pragma unroll
        for (int it = tid; it < BM * BK / 4; it += NT) {
            int r = (it * 4) / BK, c = (it * 4) % BK;
            int gr = rowBase + r;
            float4 v = make_float4(0.f, 0.f, 0.f, 0.f);
            if (gr < M) v = *(const float4*)(A + (size_t)gr * K + k0 + c);
            As[c + 0][r] = pack2(v.x, v.x);
            As[c + 1][r] = pack2(v.y, v.y);
            As[c + 2][r] = pack2(v.z, v.z);
            As[c + 3][r] = pack2(v.w, v.w);
        }
#pragma unroll
        for (int it = tid; it < BK * BN / 4; it += NT) {
            int r = (it * 4) / BN, c = (it * 4) % BN;
            *(float4*)&Bs[r][c] = *(const float4*)(B + (size_t)(k0 + r) * BN + c);
        }
        __syncthreads();
#pragma unroll
        for (int k = 0; k < BK; k++) {
            u64 ra[TM], rb[TN / 2];
#pragma unroll
            for (int i = 0; i < TM; i++) ra[i] = As[k][ty * TM + i];
#pragma unroll
            for (int j = 0; j < TN / 2; j++)
                rb[j] = *(const u64*)&Bs[k][tx * TN + 2 * j];
#pragma unroll
            for (int i = 0; i < TM; i++)
#pragma unroll
                for (int j = 0; j < TN / 2; j++)
                    acc[i][j] = ffma2(ra[i], rb[j], acc[i][j]);
        }
        __syncthreads();
    }

    float avr[TN], bvr[TN];
#pragma unroll
    for (int j = 0; j < TN; j++) {
        avr[j] = av[tx * TN + j];
        bvr[j] = bv[tx * TN + j];
    }

#pragma unroll
    for (int i = 0; i < TM; i++) {
        int gr = rowBase + ty * TM + i;
        float f[TN];
#pragma unroll
        for (int j = 0; j < TN / 2; j++) unpack2(acc[i][j], f[2 * j], f[2 * j + 1]);
        if (gr < M) {
            uint4 o;
            o.x = fp16x2(f[0], f[1]);
            o.y = fp16x2(f[2], f[3]);
            o.z = fp16x2(f[4], f[5]);
            o.w = fp16x2(f[6], f[7]);
            *(uint4*)(Ch + (size_t)gr * (BN / 2) + tx * (TN / 2)) = o;
        }
        float s = 0.f, d = 0.f;
#pragma unroll
        for (int j = 0; j < TN; j++) {
            s += f[j] * avr[j];
            d += f[j] * bvr[j];
        }
#pragma unroll
        for (int off = TG / 2; off > 0; off >>= 1) {
            s += __shfl_xor_sync(0xffffffffu, s, off);
            d += __shfl_xor_sync(0xffffffffu, d, off);
        }
        if (tx == 0 && gr < M) {
            as_out[gr] = s;
            ad_out[gr] = d;
        }
    }
}

// ======== CSR gather aggregation over fp16 features, fp32 accumulate ========
template <int H>
__global__ void agg_csr_kernel(const int* __restrict__ rowptr,
                               const int* __restrict__ esrc,
                               const float* __restrict__ as,
                               const float* __restrict__ ad,
                               const uint32_t* __restrict__ hh,
                               const float* __restrict__ bias,
                               float* __restrict__ out, int n) {
    constexpr int G = H / 8;        // lanes per edge (uint4 = 8 fp16 each)
    constexpr int EPW = 32 / G;     // edges in flight per warp
    int warp = (blockIdx.x * blockDim.x + threadIdx.x) >> 5;
    if (warp >= n) return;
    int lane = threadIdx.x & 31;
    int eslot = lane / G;
    int part = lane % G;

    int beg = __ldg(&rowptr[warp]);
    int end = __ldg(&rowptr[warp + 1]);
    float add = __ldg(&ad[warp]);

    float acc[8] = {0.f, 0.f, 0.f, 0.f, 0.f, 0.f, 0.f, 0.f};
    float den = 0.f;
    for (int i = beg + eslot; i < end; i += EPW) {
        int s = __ldg(&esrc[i]);
        float v = __ldg(&as[s]) + add;
        v = (v > 0.f) ? v : 0.2f * v;
        float w = __expf(v);
        uint4 hv = __ldg((const uint4*)(hh + (size_t)s * (H / 2)) + part);
        float2 f0 = h2f(hv.x), f1 = h2f(hv.y), f2 = h2f(hv.z), f3 = h2f(hv.w);
        acc[0] += w * f0.x; acc[1] += w * f0.y;
        acc[2] += w * f1.x; acc[3] += w * f1.y;
        acc[4] += w * f2.x; acc[5] += w * f2.y;
        acc[6] += w * f3.x; acc[7] += w * f3.y;
        den += w;
    }
#pragma unroll
    for (int off = G; off < 32; off <<= 1) {
#pragma unroll
        for (int j = 0; j < 8; j++)
            acc[j] += __shfl_xor_sync(0xffffffffu, acc[j], off);
        den += __shfl_xor_sync(0xffffffffu, den, off);
    }
    if (eslot == 0) {
        float inv = 1.f / den;
        float* op = out + (size_t)warp * H + part * 8;
        float4 b0 = __ldg(&((const float4*)bias)[part * 2]);
        float4 b1 = __ldg(&((const float4*)bias)[part * 2 + 1]);
        float4 o0, o1;
        o0.x = fmaxf(acc[0] * inv + b0.x, 0.f);
        o0.y = fmaxf(acc[1] * inv + b0.y, 0.f);
        o0.z = fmaxf(acc[2] * inv + b0.z, 0.f);
        o0.w = fmaxf(acc[3] * inv + b0.w, 0.f);
        o1.x = fmaxf(acc[4] * inv + b1.x, 0.f);
        o1.y = fmaxf(acc[5] * inv + b1.y, 0.f);
        o1.z = fmaxf(acc[6] * inv + b1.z, 0.f);
        o1.w = fmaxf(acc[7] * inv + b1.w, 0.f);
        ((float4*)op)[0] = o0;
        ((float4*)op)[1] = o1;
    }
}

// ---------------- final head ----------------
__global__ void final_kernel(const float* __restrict__ x2,
                             const float* __restrict__ Wfc,
                             const float* __restrict__ bfc,
                             float* __restrict__ out, int n) {
    int i = blockIdx.x * blockDim.x + threadIdx.x;
    if (i >= n) return;
    const float4* hp = (const float4*)(x2 + (size_t)i * 32);
    float s = 0.f;
#pragma unroll
    for (int j = 0; j < 8; j++) {
        float4 a = hp[j];
        float4 w = ((const float4*)Wfc)[j];
        s += a.x * w.x + a.y * w.y + a.z * w.z + a.w * w.w;
    }
    out[i] = s + bfc[0];
}

// ---------------- launch ----------------
extern "C" void kernel_launch(void* const* d_in, const int* in_sizes, int n_in,
                              void* d_out, int out_size) {
    const float* x   = (const float*)d_in[0];
    const int*   ei  = (const int*)d_in[1];
    const float* W1  = (const float*)d_in[2];
    const float* as1 = (const float*)d_in[3];
    const float* ad1 = (const float*)d_in[4];
    const float* b1  = (const float*)d_in[5];
    const float* W2  = (const float*)d_in[6];
    const float* as2 = (const float*)d_in[7];
    const float* ad2 = (const float*)d_in[8];
    const float* b2  = (const float*)d_in[9];
    const float* Wfc = (const float*)d_in[10];
    const float* bfc = (const float*)d_in[11];
    float* out = (float*)d_out;

    const int N  = in_sizes[0] / 256;
    const int E  = in_sizes[1] / 2;
    const int ET = E + N;

    float *x1, *x2, *asb, *adb;
    uint32_t *h1h, *h2h;
    int *deg, *rowptr, *cur, *blk, *esrc;
    uint4* bf;
    cudaGetSymbolAddress((void**)&h1h, g_h1h);
    cudaGetSymbolAddress((void**)&x1, g_x1);
    cudaGetSymbolAddress((void**)&h2h, g_h2h);
    cudaGetSymbolAddress((void**)&x2, g_x2);
    cudaGetSymbolAddress((void**)&asb, g_as);
    cudaGetSymbolAddress((void**)&adb, g_ad);
    cudaGetSymbolAddress((void**)&deg, g_deg);
    cudaGetSymbolAddress((void**)&rowptr, g_rowptr);
    cudaGetSymbolAddress((void**)&cur, g_cur);
    cudaGetSymbolAddress((void**)&blk, g_blk);
    cudaGetSymbolAddress((void**)&esrc, g_esrc);
    cudaGetSymbolAddress((void**)&bf, g_bf);

    static cudaStream_t s2 = nullptr;
    static cudaEvent_t evFork = nullptr, evJoin = nullptr;
    if (!s2) {
        cudaStreamCreateWithFlags(&s2, cudaStreamNonBlocking);
        cudaEventCreateWithFlags(&evFork, cudaEventDisableTiming);
        cudaEventCreateWithFlags(&evJoin, cudaEventDisableTiming);
    }

    const int T = 256;
    auto nb = [](long long n, int t) { return (int)((n + t - 1) / t); };
    const int nScanBlk = nb(N, 1024);

    // ---------- fork: CSR build starts on side stream ----------
    cudaEventRecord(evFork, 0);
    cudaStreamWaitEvent(s2, evFork, 0);
    cudaMemsetAsync(deg, 0, (size_t)N * sizeof(int), s2);
    hist_kernel<<<nb(ET, T), T, 0, s2>>>(ei, E, ET, deg);               // 1
    scan_block_kernel<<<nScanBlk, 1024, 0, s2>>>(deg, rowptr, blk, N);  // 2

    // ---------- main stream: preconvert W1, then mma gemm1 (4th launch) ----
    preconv_b_kernel<<<16, 256>>>(W1, bf);                              // 3
    gemm1_mma_kernel<<<nb(N, 256), 256>>>(x, bf, h1h, N, as1, ad1,
                                          asb, adb);                    // 4

    // ---------- side stream: rest of CSR build ----------
    scan_tops_kernel<<<1, 128, 0, s2>>>(blk, nScanBlk);                 // 5
    scan_add_kernel<<<nScanBlk, 1024, 0, s2>>>(rowptr, blk, deg, cur, N); // 6
    scatter_kernel<<<nb(ET, T), T, 0, s2>>>(ei, E, ET, cur, esrc);      // 7
    cudaEventRecord(evJoin, s2);

    // ---------- join, then aggregation ----------
    cudaStreamWaitEvent(0, evJoin, 0);
    agg_csr_kernel<64>
        <<<nb((long long)N * 32, T), T>>>(rowptr, esrc, asb, adb, h1h, b1, x1, N);

    // ---------- layer 2 (H=32) ----------
    gemm_fused_kernel<128, 32, 32, 4, 8>
        <<<nb(N, 128), dim3(4, 32)>>>(x1, W2, h2h, N, 64, as2, ad2, asb, adb);
    agg_csr_kernel<32>
        <<<nb((long long)N * 32, T), T>>>(rowptr, esrc, asb, adb, h2h, b2, x2, N);

    // ---------- head ----------
    final_kernel<<<nb(N, T), T>>>(x2, Wfc, bfc, out, N);
}

// round 11
// speedup vs baseline: 1.0474x; 1.0474x over previous
#include <cuda_runtime.h>
#include <cuda_bf16.h>
#include <cuda_fp16.h>
#include <cstdint>

#define NN 100000
#define EMAXC 1700000

// ---------------- scratch (static device globals; no allocs) ----------------
__device__ uint32_t g_h1h[NN * 32];  // layer1 features, fp16x2-packed (64 cols)
__device__ float    g_x1[NN * 64];   // layer1 output (f32, gemm2 input)
__device__ uint32_t g_h2h[NN * 16];  // layer2 features, fp16x2-packed (32 cols)
__device__ float    g_x2[NN * 32];   // layer2 output (f32)
__device__ float    g_as[NN];
__device__ float    g_ad[NN];
__device__ int      g_deg[NN];
__device__ int      g_rowptr[NN + 1];
__device__ int      g_cur[NN];
__device__ int      g_blk[128];
__device__ int      g_esrc[EMAXC];
__device__ uint4    g_bf[4096];      // preconverted W1 fragments

typedef unsigned long long u64;

__device__ __forceinline__ u64 ffma2(u64 a, u64 b, u64 c) {
    u64 d;
    asm("fma.rn.f32x2 %0, %1, %2, %3;" : "=l"(d) : "l"(a), "l"(b), "l"(c));
    return d;
}
__device__ __forceinline__ u64 pack2(float x, float y) {
    u64 r;
    asm("mov.b64 %0, {%1,%2};" : "=l"(r) : "f"(x), "f"(y));
    return r;
}
__device__ __forceinline__ void unpack2(u64 v, float& x, float& y) {
    asm("mov.b64 {%0,%1}, %2;" : "=f"(x), "=f"(y) : "l"(v));
}

__device__ __forceinline__ void mma16816(float* c, uint32_t a0, uint32_t a1,
                                         uint32_t a2, uint32_t a3,
                                         uint32_t b0, uint32_t b1) {
    asm volatile(
        "mma.sync.aligned.m16n8k16.row.col.f32.bf16.bf16.f32 "
        "{%0,%1,%2,%3}, {%4,%5,%6,%7}, {%8,%9}, {%0,%1,%2,%3};"
        : "+f"(c[0]), "+f"(c[1]), "+f"(c[2]), "+f"(c[3])
        : "r"(a0), "r"(a1), "r"(a2), "r"(a3), "r"(b0), "r"(b1));
}

__device__ __forceinline__ uint32_t bfhi2(float x, float y) {
    __nv_bfloat162 h = __floats2bfloat162_rn(x, y);
    return *(uint32_t*)&h;
}
__device__ __forceinline__ uint32_t bflo2(float x, float y, uint32_t hi) {
    __nv_bfloat162 h = *(__nv_bfloat162*)&hi;
    float2 f = __bfloat1622float2(h);
    __nv_bfloat162 l = __floats2bfloat162_rn(x - f.x, y - f.y);
    return *(uint32_t*)&l;
}
__device__ __forceinline__ uint32_t fp16x2(float x, float y) {
    __half2 h = __floats2half2_rn(x, y);
    return *(uint32_t*)&h;
}
__device__ __forceinline__ float2 h2f(uint32_t u) {
    return __half22float2(*(__half2*)&u);
}

// precompute W1 fragments: idx = kk*256 + n*4 + tig
__global__ void preconv_b_kernel(const float* __restrict__ W,
                                 uint4* __restrict__ Bf) {
    int idx = blockIdx.x * 256 + threadIdx.x;
    if (idx >= 4096) return;
    int tig = idx & 3, n = (idx >> 2) & 63, kk = idx >> 8;
    int k = kk * 16 + 2 * tig;
    float w00 = __ldg(&W[(size_t)k * 64 + n]);
    float w01 = __ldg(&W[(size_t)(k + 1) * 64 + n]);
    float w10 = __ldg(&W[(size_t)(k + 8) * 64 + n]);
    float w11 = __ldg(&W[(size_t)(k + 9) * 64 + n]);
    uint4 o;
    o.x = bfhi2(w00, w01);
    o.y = bfhi2(w10, w11);
    o.z = bflo2(w00, w01, o.x);
    o.w = bflo2(w10, w11, o.y);
    Bf[idx] = o;
}

// ==== gemm1 (R8 structure, 16 rows/warp): h1h = fp16(x @ W1) + alphas ======
__global__ void __launch_bounds__(256)
gemm1_mma_kernel(const float* __restrict__ A,   // [M,256]
                 const uint4* __restrict__ Bf,  // preconverted fragments
                 uint32_t* __restrict__ Ch,     // [M,32] fp16x2
                 int M,
                 const float* __restrict__ av, const float* __restrict__ bv,
                 float* __restrict__ as_out, float* __restrict__ ad_out) {
    const int tid = threadIdx.x;
    const int wid = tid >> 5, lane = tid & 31;
    const int gid = lane >> 2, tig = lane & 3;
    const int rowBase = blockIdx.x * 128;

    const int grLo = rowBase + wid * 16 + gid;
    const int grHi = grLo + 8;
    const float* a0p = A + (size_t)min(grLo, M - 1) * 256 + 2 * tig;
    const float* a1p = A + (size_t)min(grHi, M - 1) * 256 + 2 * tig;

    float acc[8][4];
#pragma unroll
    for (int t = 0; t < 8; t++)
#pragma unroll
        for (int j = 0; j < 4; j++) acc[t][j] = 0.f;

#pragma unroll 4
    for (int kk = 0; kk < 16; kk++) {
        float2 v00 = __ldg((const float2*)(a0p + kk * 16));
        float2 v01 = __ldg((const float2*)(a0p + kk * 16 + 8));
        float2 v10 = __ldg((const float2*)(a1p + kk * 16));
        float2 v11 = __ldg((const float2*)(a1p + kk * 16 + 8));
        uint32_t ah0 = bfhi2(v00.x, v00.y), ah1 = bfhi2(v10.x, v10.y);
        uint32_t ah2 = bfhi2(v01.x, v01.y), ah3 = bfhi2(v11.x, v11.y);
        uint32_t al0 = bflo2(v00.x, v00.y, ah0), al1 = bflo2(v10.x, v10.y, ah1);
        uint32_t al2 = bflo2(v01.x, v01.y, ah2), al3 = bflo2(v11.x, v11.y, ah3);
        const uint4* bp = Bf + kk * 256 + gid * 4 + tig;
#pragma unroll
        for (int nt = 0; nt < 8; nt++) {
            uint4 b = __ldg(bp + nt * 32);
            mma16816(acc[nt], ah0, ah1, ah2, ah3, b.x, b.y);  // hi*hi
            mma16816(acc[nt], ah0, ah1, ah2, ah3, b.z, b.w);  // hi*lo
            mma16816(acc[nt], al0, al1, al2, al3, b.x, b.y);  // lo*hi
        }
    }

    // ---- epilogue: fp16 store + alpha dots ----
    float sLo = 0.f, dLo = 0.f, sHi = 0.f, dHi = 0.f;
#pragma unroll
    for (int nt = 0; nt < 8; nt++) {
        int col = nt * 8 + 2 * tig;
        float a0 = __ldg(&av[col]), a1 = __ldg(&av[col + 1]);
        float b0 = __ldg(&bv[col]), b1 = __ldg(&bv[col + 1]);
        if (grLo < M)
            Ch[(size_t)grLo * 32 + nt * 4 + tig] = fp16x2(acc[nt][0], acc[nt][1]);
        if (grHi < M)
            Ch[(size_t)grHi * 32 + nt * 4 + tig] = fp16x2(acc[nt][2], acc[nt][3]);
        sLo += acc[nt][0] * a0 + acc[nt][1] * a1;
        dLo += acc[nt][0] * b0 + acc[nt][1] * b1;
        sHi += acc[nt][2] * a0 + acc[nt][3] * a1;
        dHi += acc[nt][2] * b0 + acc[nt][3] * b1;
    }
#pragma unroll
    for (int off = 1; off < 4; off <<= 1) {
        sLo += __shfl_xor_sync(0xffffffffu, sLo, off);
        dLo += __shfl_xor_sync(0xffffffffu, dLo, off);
        sHi += __shfl_xor_sync(0xffffffffu, sHi, off);
        dHi += __shfl_xor_sync(0xffffffffu, dHi, off);
    }
    if (tig == 0) {
        if (grLo < M) { as_out[grLo] = sLo; ad_out[grLo] = dLo; }
        if (grHi < M) { as_out[grHi] = sHi; ad_out[grHi] = dHi; }
    }
}

// ======================= CSR build =======================
__global__ void hist_kernel(const int* __restrict__ ei, int E, int nE,
                            int* __restrict__ deg) {
    int e = blockIdx.x * blockDim.x + threadIdx.x;
    if (e >= nE) return;
    int d = (e < E) ? __ldg(&ei[E + e]) : e - E;
    atomicAdd(&deg[d], 1);
}

__global__ void scan_block_kernel(const int* __restrict__ deg,
                                  int* __restrict__ rowptr,
                                  int* __restrict__ blk, int n) {
    __shared__ int sh[1024];
    int i = blockIdx.x * 1024 + threadIdx.x;
    int v = (i < n) ? deg[i] : 0;
    sh[threadIdx.x] = v;
    __syncthreads();
#pragma unroll
    for (int off = 1; off < 1024; off <<= 1) {
        int t = (threadIdx.x >= off) ? sh[threadIdx.x - off] : 0;
        __syncthreads();
        sh[threadIdx.x] += t;
        __syncthreads();
    }
    if (i < n) rowptr[i + 1] = sh[threadIdx.x];
    if (threadIdx.x == 1023) blk[blockIdx.x] = sh[1023];
}

__global__ void scan_tops_kernel(int* __restrict__ blk, int nb) {
    __shared__ int sh[128];
    int v = (threadIdx.x < nb) ? blk[threadIdx.x] : 0;
    sh[threadIdx.x] = v;
    __syncthreads();
#pragma unroll
    for (int off = 1; off < 128; off <<= 1) {
        int t = (threadIdx.x >= off) ? sh[threadIdx.x - off] : 0;
        __syncthreads();
        sh[threadIdx.x] += t;
        __syncthreads();
    }
    if (threadIdx.x < nb)
        blk[threadIdx.x] = (threadIdx.x == 0) ? 0 : sh[threadIdx.x - 1];
}

__global__ void scan_add_kernel(int* __restrict__ rowptr,
                                const int* __restrict__ blk,
                                const int* __restrict__ deg,
                                int* __restrict__ cur, int n) {
    int i = blockIdx.x * 1024 + threadIdx.x;
    if (i >= n) return;
    int v = rowptr[i + 1] + blk[i / 1024];
    rowptr[i + 1] = v;
    cur[i] = v - deg[i];
    if (i == 0) rowptr[0] = 0;
}

__global__ void scatter_kernel(const int* __restrict__ ei, int E, int nE,
                               int* __restrict__ cur, int* __restrict__ esrc) {
    int e = blockIdx.x * blockDim.x + threadIdx.x;
    if (e >= nE) return;
    int s, d;
    if (e < E) { s = __ldg(&ei[e]); d = __ldg(&ei[E + e]); } else { s = d = e - E; }
    int p = atomicAdd(&cur[d], 1);
    esrc[p] = s;
}

// ---------------- FFMA2 GEMM (layer 2), fp16 output + alpha epilogue -------
template <int BM, int BN, int BK, int TM, int TN>
__global__ void gemm_fused_kernel(const float* __restrict__ A,
                                  const float* __restrict__ B,
                                  uint32_t* __restrict__ Ch, int M, int K,
                                  const float* __restrict__ av,
                                  const float* __restrict__ bv,
                                  float* __restrict__ as_out,
                                  float* __restrict__ ad_out) {
    __shared__ u64  As[BK][BM + 1];
    __shared__ float Bs[BK][BN];
    const int tx = threadIdx.x, ty = threadIdx.y;
    constexpr int TG = BN / TN;
    const int tid = ty * TG + tx;
    constexpr int NT = TG * (BM / TM);
    const int rowBase = blockIdx.x * BM;

    u64 acc[TM][TN / 2];
#pragma unroll
    for (int i = 0; i < TM; i++)
#pragma unroll
        for (int j = 0; j < TN / 2; j++) acc[i][j] = 0ull;

    for (int k0 = 0; k0 < K; k0 += BK) {
#pragma unroll
        for (int it = tid; it < BM * BK / 4; it += NT) {
            int r = (it * 4) / BK, c = (it * 4) % BK;
            int gr = rowBase + r;
            float4 v = make_float4(0.f, 0.f, 0.f, 0.f);
            if (gr < M) v = *(const float4*)(A + (size_t)gr * K + k0 + c);
            As[c + 0][r] = pack2(v.x, v.x);
            As[c + 1][r] = pack2(v.y, v.y);
            As[c + 2][r] = pack2(v.z, v.z);
            As[c + 3][r] = pack2(v.w, v.w);
        }
#pragma unroll
        for (int it = tid; it < BK * BN / 4; it += NT) {
            int r = (it * 4) / BN, c = (it * 4) % BN;
            *(float4*)&Bs[r][c] = *(const float4*)(B + (size_t)(k0 + r) * BN + c);
        }
        __syncthreads();
#pragma unroll
        for (int k = 0; k < BK; k++) {
            u64 ra[TM], rb[TN / 2];
#pragma unroll
            for (int i = 0; i < TM; i++) ra[i] = As[k][ty * TM + i];
#pragma unroll
            for (int j = 0; j < TN / 2; j++)
                rb[j] = *(const u64*)&Bs[k][tx * TN + 2 * j];
#pragma unroll
            for (int i = 0; i < TM; i++)
#pragma unroll
                for (int j = 0; j < TN / 2; j++)
                    acc[i][j] = ffma2(ra[i], rb[j], acc[i][j]);
        }
        __syncthreads();
    }

    float avr[TN], bvr[TN];
#pragma unroll
    for (int j = 0; j < TN; j++) {
        avr[j] = av[tx * TN + j];
        bvr[j] = bv[tx * TN + j];
    }

#pragma unroll
    for (int i = 0; i < TM; i++) {
        int gr = rowBase + ty * TM + i;
        float f[TN];
#pragma unroll
        for (int j = 0; j < TN / 2; j++) unpack2(acc[i][j], f[2 * j], f[2 * j + 1]);
        if (gr < M) {
            uint4 o;
            o.x = fp16x2(f[0], f[1]);
            o.y = fp16x2(f[2], f[3]);
            o.z = fp16x2(f[4], f[5]);
            o.w = fp16x2(f[6], f[7]);
            *(uint4*)(Ch + (size_t)gr * (BN / 2) + tx * (TN / 2)) = o;
        }
        float s = 0.f, d = 0.f;
#pragma unroll
        for (int j = 0; j < TN; j++) {
            s += f[j] * avr[j];
            d += f[j] * bvr[j];
        }
#pragma unroll
        for (int off = TG / 2; off > 0; off >>= 1) {
            s += __shfl_xor_sync(0xffffffffu, s, off);
            d += __shfl_xor_sync(0xffffffffu, d, off);
        }
        if (tx == 0 && gr < M) {
            as_out[gr] = s;
            ad_out[gr] = d;
        }
    }
}

// ======== CSR gather aggregation over fp16 features, fp32 accumulate ========
template <int H>
__global__ void agg_csr_kernel(const int* __restrict__ rowptr,
                               const int* __restrict__ esrc,
                               const float* __restrict__ as,
                               const float* __restrict__ ad,
                               const uint32_t* __restrict__ hh,
                               const float* __restrict__ bias,
                               float* __restrict__ out, int n) {
    constexpr int G = H / 8;        // lanes per edge (uint4 = 8 fp16 each)
    constexpr int EPW = 32 / G;     // edges in flight per warp
    int warp = (blockIdx.x * blockDim.x + threadIdx.x) >> 5;
    if (warp >= n) return;
    int lane = threadIdx.x & 31;
    int eslot = lane / G;
    int part = lane % G;

    int beg = __ldg(&rowptr[warp]);
    int end = __ldg(&rowptr[warp + 1]);
    float add = __ldg(&ad[warp]);

    float acc[8] = {0.f, 0.f, 0.f, 0.f, 0.f, 0.f, 0.f, 0.f};
    float den = 0.f;
    for (int i = beg + eslot; i < end; i += EPW) {
        int s = __ldg(&esrc[i]);
        float v = __ldg(&as[s]) + add;
        v = (v > 0.f) ? v : 0.2f * v;
        float w = __expf(v);
        uint4 hv = __ldg((const uint4*)(hh + (size_t)s * (H / 2)) + part);
        float2 f0 = h2f(hv.x), f1 = h2f(hv.y), f2 = h2f(hv.z), f3 = h2f(hv.w);
        acc[0] += w * f0.x; acc[1] += w * f0.y;
        acc[2] += w * f1.x; acc[3] += w * f1.y;
        acc[4] += w * f2.x; acc[5] += w * f2.y;
        acc[6] += w * f3.x; acc[7] += w * f3.y;
        den += w;
    }
#pragma unroll
    for (int off = G; off < 32; off <<= 1) {
#pragma unroll
        for (int j = 0; j < 8; j++)
            acc[j] += __shfl_xor_sync(0xffffffffu, acc[j], off);
        den += __shfl_xor_sync(0xffffffffu, den, off);
    }
    if (eslot == 0) {
        float inv = 1.f / den;
        float* op = out + (size_t)warp * H + part * 8;
        float4 b0 = __ldg(&((const float4*)bias)[part * 2]);
        float4 b1 = __ldg(&((const float4*)bias)[part * 2 + 1]);
        float4 o0, o1;
        o0.x = fmaxf(acc[0] * inv + b0.x, 0.f);
        o0.y = fmaxf(acc[1] * inv + b0.y, 0.f);
        o0.z = fmaxf(acc[2] * inv + b0.z, 0.f);
        o0.w = fmaxf(acc[3] * inv + b0.w, 0.f);
        o1.x = fmaxf(acc[4] * inv + b1.x, 0.f);
        o1.y = fmaxf(acc[5] * inv + b1.y, 0.f);
        o1.z = fmaxf(acc[6] * inv + b1.z, 0.f);
        o1.w = fmaxf(acc[7] * inv + b1.w, 0.f);
        ((float4*)op)[0] = o0;
        ((float4*)op)[1] = o1;
    }
}

// ---------------- final head ----------------
__global__ void final_kernel(const float* __restrict__ x2,
                             const float* __restrict__ Wfc,
                             const float* __restrict__ bfc,
                             float* __restrict__ out, int n) {
    int i = blockIdx.x * blockDim.x + threadIdx.x;
    if (i >= n) return;
    const float4* hp = (const float4*)(x2 + (size_t)i * 32);
    float s = 0.f;
#pragma unroll
    for (int j = 0; j < 8; j++) {
        float4 a = hp[j];
        float4 w = ((const float4*)Wfc)[j];
        s += a.x * w.x + a.y * w.y + a.z * w.z + a.w * w.w;
    }
    out[i] = s + bfc[0];
}

// ---------------- launch ----------------
extern "C" void kernel_launch(void* const* d_in, const int* in_sizes, int n_in,
                              void* d_out, int out_size) {
    const float* x   = (const float*)d_in[0];
    const int*   ei  = (const int*)d_in[1];
    const float* W1  = (const float*)d_in[2];
    const float* as1 = (const float*)d_in[3];
    const float* ad1 = (const float*)d_in[4];
    const float* b1  = (const float*)d_in[5];
    const float* W2  = (const float*)d_in[6];
    const float* as2 = (const float*)d_in[7];
    const float* ad2 = (const float*)d_in[8];
    const float* b2  = (const float*)d_in[9];
    const float* Wfc = (const float*)d_in[10];
    const float* bfc = (const float*)d_in[11];
    float* out = (float*)d_out;

    const int N  = in_sizes[0] / 256;
    const int E  = in_sizes[1] / 2;
    const int ET = E + N;

    float *x1, *x2, *asb, *adb;
    uint32_t *h1h, *h2h;
    int *deg, *rowptr, *cur, *blk, *esrc;
    uint4* bf;
    cudaGetSymbolAddress((void**)&h1h, g_h1h);
    cudaGetSymbolAddress((void**)&x1, g_x1);
    cudaGetSymbolAddress((void**)&h2h, g_h2h);
    cudaGetSymbolAddress((void**)&x2, g_x2);
    cudaGetSymbolAddress((void**)&asb, g_as);
    cudaGetSymbolAddress((void**)&adb, g_ad);
    cudaGetSymbolAddress((void**)&deg, g_deg);
    cudaGetSymbolAddress((void**)&rowptr, g_rowptr);
    cudaGetSymbolAddress((void**)&cur, g_cur);
    cudaGetSymbolAddress((void**)&blk, g_blk);
    cudaGetSymbolAddress((void**)&esrc, g_esrc);
    cudaGetSymbolAddress((void**)&bf, g_bf);

    static cudaStream_t s2 = nullptr;
    static cudaEvent_t evFork = nullptr, evJoin = nullptr;
    if (!s2) {
        cudaStreamCreateWithFlags(&s2, cudaStreamNonBlocking);
        cudaEventCreateWithFlags(&evFork, cudaEventDisableTiming);
        cudaEventCreateWithFlags(&evJoin, cudaEventDisableTiming);
    }

    const int T = 256;
    auto nb = [](long long n, int t) { return (int)((n + t - 1) / t); };
    const int nScanBlk = nb(N, 1024);

    // ---------- fork: CSR build starts on side stream ----------
    cudaEventRecord(evFork, 0);
    cudaStreamWaitEvent(s2, evFork, 0);
    cudaMemsetAsync(deg, 0, (size_t)N * sizeof(int), s2);
    hist_kernel<<<nb(ET, T), T, 0, s2>>>(ei, E, ET, deg);               // 1
    scan_block_kernel<<<nScanBlk, 1024, 0, s2>>>(deg, rowptr, blk, N);  // 2

    // ---------- main stream: preconvert W1, then mma gemm1 (4th launch) ----
    preconv_b_kernel<<<16, 256>>>(W1, bf);                              // 3
    gemm1_mma_kernel<<<nb(N, 128), 256>>>(x, bf, h1h, N, as1, ad1,
                                          asb, adb);                    // 4

    // ---------- side stream: rest of CSR build ----------
    scan_tops_kernel<<<1, 128, 0, s2>>>(blk, nScanBlk);                 // 5
    scan_add_kernel<<<nScanBlk, 1024, 0, s2>>>(rowptr, blk, deg, cur, N); // 6
    scatter_kernel<<<nb(ET, T), T, 0, s2>>>(ei, E, ET, cur, esrc);      // 7
    cudaEventRecord(evJoin, s2);

    // ---------- join, then aggregation ----------
    cudaStreamWaitEvent(0, evJoin, 0);
    agg_csr_kernel<64>
        <<<nb((long long)N * 32, T), T>>>(rowptr, esrc, asb, adb, h1h, b1, x1, N);

    // ---------- layer 2 (H=32) ----------
    gemm_fused_kernel<128, 32, 32, 4, 8>
        <<<nb(N, 128), dim3(4, 32)>>>(x1, W2, h2h, N, 64, as2, ad2, asb, adb);
    agg_csr_kernel<32>
        <<<nb((long long)N * 32, T), T>>>(rowptr, esrc, asb, adb, h2h, b2, x2, N);

    // ---------- head ----------
    final_kernel<<<nb(N, T), T>>>(x2, Wfc, bfc, out, N);
}

// round 12
// speedup vs baseline: 1.1804x; 1.1270x over previous
#include <cuda_runtime.h>
#include <cuda_bf16.h>
#include <cuda_fp16.h>
#include <cstdint>

#define NN 100000
#define EMAXC 1700000

// ---------------- scratch (static device globals; no allocs) ----------------
__device__ uint32_t g_h1h[NN * 32];  // layer1 features, fp16x2 (64 cols)
__device__ uint32_t g_x1h[NN * 32];  // layer1 output, fp16x2 (64 cols)
__device__ uint32_t g_h2h[NN * 16];  // layer2 features, fp16x2 (32 cols)
__device__ float    g_as[NN];
__device__ float    g_ad[NN];
__device__ int      g_deg[NN];
__device__ int      g_rowptr[NN + 1];
__device__ int      g_cur[NN];
__device__ int      g_blk[128];
__device__ int      g_esrc[EMAXC];
__device__ uint4    g_bf[4096];      // W1 fragments [kk16][n64][tig4]
__device__ uint4    g_bf2[512];      // W2 fragments [kk4][n32][tig4]

typedef unsigned long long u64;

__device__ __forceinline__ void mma_bf16(float* c, uint32_t a0, uint32_t a1,
                                         uint32_t a2, uint32_t a3,
                                         uint32_t b0, uint32_t b1) {
    asm volatile(
        "mma.sync.aligned.m16n8k16.row.col.f32.bf16.bf16.f32 "
        "{%0,%1,%2,%3}, {%4,%5,%6,%7}, {%8,%9}, {%0,%1,%2,%3};"
        : "+f"(c[0]), "+f"(c[1]), "+f"(c[2]), "+f"(c[3])
        : "r"(a0), "r"(a1), "r"(a2), "r"(a3), "r"(b0), "r"(b1));
}
__device__ __forceinline__ void mma_f16(float* c, uint32_t a0, uint32_t a1,
                                        uint32_t a2, uint32_t a3,
                                        uint32_t b0, uint32_t b1) {
    asm volatile(
        "mma.sync.aligned.m16n8k16.row.col.f32.f16.f16.f32 "
        "{%0,%1,%2,%3}, {%4,%5,%6,%7}, {%8,%9}, {%0,%1,%2,%3};"
        : "+f"(c[0]), "+f"(c[1]), "+f"(c[2]), "+f"(c[3])
        : "r"(a0), "r"(a1), "r"(a2), "r"(a3), "r"(b0), "r"(b1));
}

__device__ __forceinline__ uint32_t bfhi2(float x, float y) {
    __nv_bfloat162 h = __floats2bfloat162_rn(x, y);
    return *(uint32_t*)&h;
}
__device__ __forceinline__ uint32_t bflo2(float x, float y, uint32_t hi) {
    __nv_bfloat162 h = *(__nv_bfloat162*)&hi;
    float2 f = __bfloat1622float2(h);
    __nv_bfloat162 l = __floats2bfloat162_rn(x - f.x, y - f.y);
    return *(uint32_t*)&l;
}
__device__ __forceinline__ uint32_t fp16x2(float x, float y) {
    __half2 h = __floats2half2_rn(x, y);
    return *(uint32_t*)&h;
}
__device__ __forceinline__ uint32_t fp16lo2(float x, float y, uint32_t hi) {
    __half2 h = *(__half2*)&hi;
    float2 f = __half22float2(h);
    __half2 l = __floats2half2_rn(x - f.x, y - f.y);
    return *(uint32_t*)&l;
}
__device__ __forceinline__ float2 h2f(uint32_t u) {
    return __half22float2(*(__half2*)&u);
}

// precompute W1 fragments (bf16 hi/lo): idx = kk*256 + n*4 + tig
__global__ void preconv_b_kernel(const float* __restrict__ W,
                                 uint4* __restrict__ Bf) {
    int idx = blockIdx.x * 256 + threadIdx.x;
    if (idx >= 4096) return;
    int tig = idx & 3, n = (idx >> 2) & 63, kk = idx >> 8;
    int k = kk * 16 + 2 * tig;
    float w00 = __ldg(&W[(size_t)k * 64 + n]);
    float w01 = __ldg(&W[(size_t)(k + 1) * 64 + n]);
    float w10 = __ldg(&W[(size_t)(k + 8) * 64 + n]);
    float w11 = __ldg(&W[(size_t)(k + 9) * 64 + n]);
    uint4 o;
    o.x = bfhi2(w00, w01);
    o.y = bfhi2(w10, w11);
    o.z = bflo2(w00, w01, o.x);
    o.w = bflo2(w10, w11, o.y);
    Bf[idx] = o;
}

// precompute W2 fragments (fp16 hi/lo): idx = kk*128 + n*4 + tig; W2 [64,32]
__global__ void preconv_b2_kernel(const float* __restrict__ W,
                                  uint4* __restrict__ Bf) {
    int idx = threadIdx.x;
    if (idx >= 512) return;
    int tig = idx & 3, n = (idx >> 2) & 31, kk = idx >> 7;
    int k = kk * 16 + 2 * tig;
    float w00 = __ldg(&W[(size_t)k * 32 + n]);
    float w01 = __ldg(&W[(size_t)(k + 1) * 32 + n]);
    float w10 = __ldg(&W[(size_t)(k + 8) * 32 + n]);
    float w11 = __ldg(&W[(size_t)(k + 9) * 32 + n]);
    uint4 o;
    o.x = fp16x2(w00, w01);
    o.y = fp16x2(w10, w11);
    o.z = fp16lo2(w00, w01, o.x);
    o.w = fp16lo2(w10, w11, o.y);
    Bf[idx] = o;
}

// ==== gemm1 (16 rows/warp, bf16 split): h1h = fp16(x @ W1) + alphas ========
__global__ void __launch_bounds__(256)
gemm1_mma_kernel(const float* __restrict__ A,   // [M,256]
                 const uint4* __restrict__ Bf,
                 uint32_t* __restrict__ Ch,     // [M,32] fp16x2
                 int M,
                 const float* __restrict__ av, const float* __restrict__ bv,
                 float* __restrict__ as_out, float* __restrict__ ad_out) {
    const int tid = threadIdx.x;
    const int wid = tid >> 5, lane = tid & 31;
    const int gid = lane >> 2, tig = lane & 3;
    const int rowBase = blockIdx.x * 128;

    const int grLo = rowBase + wid * 16 + gid;
    const int grHi = grLo + 8;
    const float* a0p = A + (size_t)min(grLo, M - 1) * 256 + 2 * tig;
    const float* a1p = A + (size_t)min(grHi, M - 1) * 256 + 2 * tig;

    float acc[8][4];
#pragma unroll
    for (int t = 0; t < 8; t++)
#pragma unroll
        for (int j = 0; j < 4; j++) acc[t][j] = 0.f;

#pragma unroll 4
    for (int kk = 0; kk < 16; kk++) {
        float2 v00 = __ldg((const float2*)(a0p + kk * 16));
        float2 v01 = __ldg((const float2*)(a0p + kk * 16 + 8));
        float2 v10 = __ldg((const float2*)(a1p + kk * 16));
        float2 v11 = __ldg((const float2*)(a1p + kk * 16 + 8));
        uint32_t ah0 = bfhi2(v00.x, v00.y), ah1 = bfhi2(v10.x, v10.y);
        uint32_t ah2 = bfhi2(v01.x, v01.y), ah3 = bfhi2(v11.x, v11.y);
        uint32_t al0 = bflo2(v00.x, v00.y, ah0), al1 = bflo2(v10.x, v10.y, ah1);
        uint32_t al2 = bflo2(v01.x, v01.y, ah2), al3 = bflo2(v11.x, v11.y, ah3);
        const uint4* bp = Bf + kk * 256 + gid * 4 + tig;
#pragma unroll
        for (int nt = 0; nt < 8; nt++) {
            uint4 b = __ldg(bp + nt * 32);
            mma_bf16(acc[nt], ah0, ah1, ah2, ah3, b.x, b.y);  // hi*hi
            mma_bf16(acc[nt], ah0, ah1, ah2, ah3, b.z, b.w);  // hi*lo
            mma_bf16(acc[nt], al0, al1, al2, al3, b.x, b.y);  // lo*hi
        }
    }

    float sLo = 0.f, dLo = 0.f, sHi = 0.f, dHi = 0.f;
#pragma unroll
    for (int nt = 0; nt < 8; nt++) {
        int col = nt * 8 + 2 * tig;
        float a0 = __ldg(&av[col]), a1 = __ldg(&av[col + 1]);
        float b0 = __ldg(&bv[col]), b1 = __ldg(&bv[col + 1]);
        if (grLo < M)
            Ch[(size_t)grLo * 32 + nt * 4 + tig] = fp16x2(acc[nt][0], acc[nt][1]);
        if (grHi < M)
            Ch[(size_t)grHi * 32 + nt * 4 + tig] = fp16x2(acc[nt][2], acc[nt][3]);
        sLo += acc[nt][0] * a0 + acc[nt][1] * a1;
        dLo += acc[nt][0] * b0 + acc[nt][1] * b1;
        sHi += acc[nt][2] * a0 + acc[nt][3] * a1;
        dHi += acc[nt][2] * b0 + acc[nt][3] * b1;
    }
#pragma unroll
    for (int off = 1; off < 4; off <<= 1) {
        sLo += __shfl_xor_sync(0xffffffffu, sLo, off);
        dLo += __shfl_xor_sync(0xffffffffu, dLo, off);
        sHi += __shfl_xor_sync(0xffffffffu, sHi, off);
        dHi += __shfl_xor_sync(0xffffffffu, dHi, off);
    }
    if (tig == 0) {
        if (grLo < M) { as_out[grLo] = sLo; ad_out[grLo] = dLo; }
        if (grHi < M) { as_out[grHi] = sHi; ad_out[grHi] = dHi; }
    }
}

// ==== gemm2 (fp16 exact MMA): h2h = fp16(x1h @ W2) + alphas ================
__global__ void __launch_bounds__(256)
gemm2_mma_kernel(const uint32_t* __restrict__ A,  // [M,32] fp16x2 (64 cols)
                 const uint4* __restrict__ Bf2,
                 uint32_t* __restrict__ Ch,       // [M,16] fp16x2 (32 cols)
                 int M,
                 const float* __restrict__ av, const float* __restrict__ bv,
                 float* __restrict__ as_out, float* __restrict__ ad_out) {
    const int tid = threadIdx.x;
    const int wid = tid >> 5, lane = tid & 31;
    const int gid = lane >> 2, tig = lane & 3;
    const int rowBase = blockIdx.x * 128;

    const int grLo = rowBase + wid * 16 + gid;
    const int grHi = grLo + 8;
    const uint32_t* a0p = A + (size_t)min(grLo, M - 1) * 32 + tig;
    const uint32_t* a1p = A + (size_t)min(grHi, M - 1) * 32 + tig;

    float acc[4][4];
#pragma unroll
    for (int t = 0; t < 4; t++)
#pragma unroll
        for (int j = 0; j < 4; j++) acc[t][j] = 0.f;

#pragma unroll
    for (int kk = 0; kk < 4; kk++) {
        uint32_t a0 = __ldg(a0p + kk * 8);
        uint32_t a2 = __ldg(a0p + kk * 8 + 4);
        uint32_t a1 = __ldg(a1p + kk * 8);
        uint32_t a3 = __ldg(a1p + kk * 8 + 4);
        const uint4* bp = Bf2 + kk * 128 + gid * 4 + tig;
#pragma unroll
        for (int nt = 0; nt < 4; nt++) {
            uint4 b = __ldg(bp + nt * 32);
            mma_f16(acc[nt], a0, a1, a2, a3, b.x, b.y);  // x1 * W2_hi
            mma_f16(acc[nt], a0, a1, a2, a3, b.z, b.w);  // x1 * W2_lo
        }
    }

    float sLo = 0.f, dLo = 0.f, sHi = 0.f, dHi = 0.f;
#pragma unroll
    for (int nt = 0; nt < 4; nt++) {
        int col = nt * 8 + 2 * tig;
        float a0 = __ldg(&av[col]), a1 = __ldg(&av[col + 1]);
        float b0 = __ldg(&bv[col]), b1 = __ldg(&bv[col + 1]);
        if (grLo < M)
            Ch[(size_t)grLo * 16 + nt * 4 + tig] = fp16x2(acc[nt][0], acc[nt][1]);
        if (grHi < M)
            Ch[(size_t)grHi * 16 + nt * 4 + tig] = fp16x2(acc[nt][2], acc[nt][3]);
        sLo += acc[nt][0] * a0 + acc[nt][1] * a1;
        dLo += acc[nt][0] * b0 + acc[nt][1] * b1;
        sHi += acc[nt][2] * a0 + acc[nt][3] * a1;
        dHi += acc[nt][2] * b0 + acc[nt][3] * b1;
    }
#pragma unroll
    for (int off = 1; off < 4; off <<= 1) {
        sLo += __shfl_xor_sync(0xffffffffu, sLo, off);
        dLo += __shfl_xor_sync(0xffffffffu, dLo, off);
        sHi += __shfl_xor_sync(0xffffffffu, sHi, off);
        dHi += __shfl_xor_sync(0xffffffffu, dHi, off);
    }
    if (tig == 0) {
        if (grLo < M) { as_out[grLo] = sLo; ad_out[grLo] = dLo; }
        if (grHi < M) { as_out[grHi] = sHi; ad_out[grHi] = dHi; }
    }
}

// ======================= CSR build =======================
__global__ void hist_kernel(const int* __restrict__ ei, int E, int nE,
                            int* __restrict__ deg) {
    int e = blockIdx.x * blockDim.x + threadIdx.x;
    if (e >= nE) return;
    int d = (e < E) ? __ldg(&ei[E + e]) : e - E;
    atomicAdd(&deg[d], 1);
}

__global__ void scan_block_kernel(const int* __restrict__ deg,
                                  int* __restrict__ rowptr,
                                  int* __restrict__ blk, int n) {
    __shared__ int sh[1024];
    int i = blockIdx.x * 1024 + threadIdx.x;
    int v = (i < n) ? deg[i] : 0;
    sh[threadIdx.x] = v;
    __syncthreads();
#pragma unroll
    for (int off = 1; off < 1024; off <<= 1) {
        int t = (threadIdx.x >= off) ? sh[threadIdx.x - off] : 0;
        __syncthreads();
        sh[threadIdx.x] += t;
        __syncthreads();
    }
    if (i < n) rowptr[i + 1] = sh[threadIdx.x];
    if (threadIdx.x == 1023) blk[blockIdx.x] = sh[1023];
}

__global__ void scan_tops_kernel(int* __restrict__ blk, int nb) {
    __shared__ int sh[128];
    int v = (threadIdx.x < nb) ? blk[threadIdx.x] : 0;
    sh[threadIdx.x] = v;
    __syncthreads();
#pragma unroll
    for (int off = 1; off < 128; off <<= 1) {
        int t = (threadIdx.x >= off) ? sh[threadIdx.x - off] : 0;
        __syncthreads();
        sh[threadIdx.x] += t;
        __syncthreads();
    }
    if (threadIdx.x < nb)
        blk[threadIdx.x] = (threadIdx.x == 0) ? 0 : sh[threadIdx.x - 1];
}

__global__ void scan_add_kernel(int* __restrict__ rowptr,
                                const int* __restrict__ blk,
                                const int* __restrict__ deg,
                                int* __restrict__ cur, int n) {
    int i = blockIdx.x * 1024 + threadIdx.x;
    if (i >= n) return;
    int v = rowptr[i + 1] + blk[i / 1024];
    rowptr[i + 1] = v;
    cur[i] = v - deg[i];
    if (i == 0) rowptr[0] = 0;
}

__global__ void scatter_kernel(const int* __restrict__ ei, int E, int nE,
                               int* __restrict__ cur, int* __restrict__ esrc) {
    int e = blockIdx.x * blockDim.x + threadIdx.x;
    if (e >= nE) return;
    int s, d;
    if (e < E) { s = __ldg(&ei[e]); d = __ldg(&ei[E + e]); } else { s = d = e - E; }
    int p = atomicAdd(&cur[d], 1);
    esrc[p] = s;
}

// ===== agg layer1: gather fp16 h1, softmax-avg, +bias, relu, emit fp16 x1 ===
__global__ void agg64_kernel(const int* __restrict__ rowptr,
                             const int* __restrict__ esrc,
                             const float* __restrict__ as,
                             const float* __restrict__ ad,
                             const uint32_t* __restrict__ hh,  // [n,32] fp16x2
                             const float* __restrict__ bias,
                             uint32_t* __restrict__ outh,      // [n,32] fp16x2
                             int n) {
    constexpr int G = 8, EPW = 4;
    int warp = (blockIdx.x * blockDim.x + threadIdx.x) >> 5;
    if (warp >= n) return;
    int lane = threadIdx.x & 31;
    int eslot = lane / G;
    int part = lane % G;

    int beg = __ldg(&rowptr[warp]);
    int end = __ldg(&rowptr[warp + 1]);
    float add = __ldg(&ad[warp]);

    float acc[8] = {0.f, 0.f, 0.f, 0.f, 0.f, 0.f, 0.f, 0.f};
    float den = 0.f;
    for (int i = beg + eslot; i < end; i += EPW) {
        int s = __ldg(&esrc[i]);
        float v = __ldg(&as[s]) + add;
        v = (v > 0.f) ? v : 0.2f * v;
        float w = __expf(v);
        uint4 hv = __ldg((const uint4*)(hh + (size_t)s * 32) + part);
        float2 f0 = h2f(hv.x), f1 = h2f(hv.y), f2 = h2f(hv.z), f3 = h2f(hv.w);
        acc[0] += w * f0.x; acc[1] += w * f0.y;
        acc[2] += w * f1.x; acc[3] += w * f1.y;
        acc[4] += w * f2.x; acc[5] += w * f2.y;
        acc[6] += w * f3.x; acc[7] += w * f3.y;
        den += w;
    }
#pragma unroll
    for (int off = G; off < 32; off <<= 1) {
#pragma unroll
        for (int j = 0; j < 8; j++)
            acc[j] += __shfl_xor_sync(0xffffffffu, acc[j], off);
        den += __shfl_xor_sync(0xffffffffu, den, off);
    }
    if (eslot == 0) {
        float inv = 1.f / den;
        float o[8];
#pragma unroll
        for (int j = 0; j < 8; j++)
            o[j] = fmaxf(acc[j] * inv + __ldg(&bias[part * 8 + j]), 0.f);
        uint4 pk;
        pk.x = fp16x2(o[0], o[1]);
        pk.y = fp16x2(o[2], o[3]);
        pk.z = fp16x2(o[4], o[5]);
        pk.w = fp16x2(o[6], o[7]);
        ((uint4*)(outh + (size_t)warp * 32))[part] = pk;
    }
}

// ===== agg layer2 + head: softmax-avg fp16 h2, +bias, relu, dot Wfc =========
__global__ void agg_final_kernel(const int* __restrict__ rowptr,
                                 const int* __restrict__ esrc,
                                 const float* __restrict__ as,
                                 const float* __restrict__ ad,
                                 const uint32_t* __restrict__ hh,  // [n,16]
                                 const float* __restrict__ b2,
                                 const float* __restrict__ Wfc,
                                 const float* __restrict__ bfc,
                                 float* __restrict__ out, int n) {
    constexpr int G = 4, EPW = 8;
    int warp = (blockIdx.x * blockDim.x + threadIdx.x) >> 5;
    if (warp >= n) return;
    int lane = threadIdx.x & 31;
    int eslot = lane / G;
    int part = lane % G;

    int beg = __ldg(&rowptr[warp]);
    int end = __ldg(&rowptr[warp + 1]);
    float add = __ldg(&ad[warp]);

    float acc[8] = {0.f, 0.f, 0.f, 0.f, 0.f, 0.f, 0.f, 0.f};
    float den = 0.f;
    for (int i = beg + eslot; i < end; i += EPW) {
        int s = __ldg(&esrc[i]);
        float v = __ldg(&as[s]) + add;
        v = (v > 0.f) ? v : 0.2f * v;
        float w = __expf(v);
        uint4 hv = __ldg((const uint4*)(hh + (size_t)s * 16) + part);
        float2 f0 = h2f(hv.x), f1 = h2f(hv.y), f2 = h2f(hv.z), f3 = h2f(hv.w);
        acc[0] += w * f0.x; acc[1] += w * f0.y;
        acc[2] += w * f1.x; acc[3] += w * f1.y;
        acc[4] += w * f2.x; acc[5] += w * f2.y;
        acc[6] += w * f3.x; acc[7] += w * f3.y;
        den += w;
    }
#pragma unroll
    for (int off = G; off < 32; off <<= 1) {
#pragma unroll
        for (int j = 0; j < 8; j++)
            acc[j] += __shfl_xor_sync(0xffffffffu, acc[j], off);
        den += __shfl_xor_sync(0xffffffffu, den, off);
    }
    if (eslot == 0) {  // lanes 0-3
        float inv = 1.f / den;
        float s = 0.f;
#pragma unroll
        for (int j = 0; j < 8; j++) {
            float v = fmaxf(acc[j] * inv + __ldg(&b2[part * 8 + j]), 0.f);
            s += v * __ldg(&Wfc[part * 8 + j]);
        }
        s += __shfl_xor_sync(0x0000000Fu, s, 1);
        s += __shfl_xor_sync(0x0000000Fu, s, 2);
        if (part == 0) out[warp] = s + __ldg(&bfc[0]);
    }
}

// ---------------- launch ----------------
extern "C" void kernel_launch(void* const* d_in, const int* in_sizes, int n_in,
                              void* d_out, int out_size) {
    const float* x   = (const float*)d_in[0];
    const int*   ei  = (const int*)d_in[1];
    const float* W1  = (const float*)d_in[2];
    const float* as1 = (const float*)d_in[3];
    const float* ad1 = (const float*)d_in[4];
    const float* b1  = (const float*)d_in[5];
    const float* W2  = (const float*)d_in[6];
    const float* as2 = (const float*)d_in[7];
    const float* ad2 = (const float*)d_in[8];
    const float* b2  = (const float*)d_in[9];
    const float* Wfc = (const float*)d_in[10];
    const float* bfc = (const float*)d_in[11];
    float* out = (float*)d_out;

    const int N  = in_sizes[0] / 256;
    const int E  = in_sizes[1] / 2;
    const int ET = E + N;

    float *asb, *adb;
    uint32_t *h1h, *x1h, *h2h;
    int *deg, *rowptr, *cur, *blk, *esrc;
    uint4 *bf, *bf2;
    cudaGetSymbolAddress((void**)&h1h, g_h1h);
    cudaGetSymbolAddress((void**)&x1h, g_x1h);
    cudaGetSymbolAddress((void**)&h2h, g_h2h);
    cudaGetSymbolAddress((void**)&asb, g_as);
    cudaGetSymbolAddress((void**)&adb, g_ad);
    cudaGetSymbolAddress((void**)&deg, g_deg);
    cudaGetSymbolAddress((void**)&rowptr, g_rowptr);
    cudaGetSymbolAddress((void**)&cur, g_cur);
    cudaGetSymbolAddress((void**)&blk, g_blk);
    cudaGetSymbolAddress((void**)&esrc, g_esrc);
    cudaGetSymbolAddress((void**)&bf, g_bf);
    cudaGetSymbolAddress((void**)&bf2, g_bf2);

    static cudaStream_t s2 = nullptr;
    static cudaEvent_t evFork = nullptr, evJoin = nullptr;
    if (!s2) {
        cudaStreamCreateWithFlags(&s2, cudaStreamNonBlocking);
        cudaEventCreateWithFlags(&evFork, cudaEventDisableTiming);
        cudaEventCreateWithFlags(&evJoin, cudaEventDisableTiming);
    }

    const int T = 256;
    auto nb = [](long long n, int t) { return (int)((n + t - 1) / t); };
    const int nScanBlk = nb(N, 1024);

    // ---------- fork: CSR build starts on side stream ----------
    cudaEventRecord(evFork, 0);
    cudaStreamWaitEvent(s2, evFork, 0);
    cudaMemsetAsync(deg, 0, (size_t)N * sizeof(int), s2);
    hist_kernel<<<nb(ET, T), T, 0, s2>>>(ei, E, ET, deg);               // 1
    scan_block_kernel<<<nScanBlk, 1024, 0, s2>>>(deg, rowptr, blk, N);  // 2

    // ---------- main stream: preconvert W1, then mma gemm1 (4th launch) ----
    preconv_b_kernel<<<16, 256>>>(W1, bf);                              // 3
    gemm1_mma_kernel<<<nb(N, 128), 256>>>(x, bf, h1h, N, as1, ad1,
                                          asb, adb);                    // 4

    // ---------- side stream: rest of CSR build + W2 preconvert ----------
    scan_tops_kernel<<<1, 128, 0, s2>>>(blk, nScanBlk);
    scan_add_kernel<<<nScanBlk, 1024, 0, s2>>>(rowptr, blk, deg, cur, N);
    scatter_kernel<<<nb(ET, T), T, 0, s2>>>(ei, E, ET, cur, esrc);
    preconv_b2_kernel<<<1, 512, 0, s2>>>(W2, bf2);
    cudaEventRecord(evJoin, s2);

    // ---------- join, then layer-1 aggregation (emits fp16 x1) ----------
    cudaStreamWaitEvent(0, evJoin, 0);
    agg64_kernel<<<nb((long long)N * 32, T), T>>>(rowptr, esrc, asb, adb,
                                                  h1h, b1, x1h, N);

    // ---------- layer 2: exact-fp16 MMA gemm, then fused agg+head ----------
    gemm2_mma_kernel<<<nb(N, 128), 256>>>(x1h, bf2, h2h, N, as2, ad2,
                                          asb, adb);
    agg_final_kernel<<<nb((long long)N * 32, T), T>>>(rowptr, esrc, asb, adb,
                                                      h2h, b2, Wfc, bfc,
                                                      out, N);
}